// round 11
// baseline (speedup 1.0000x reference)
#include <cuda_runtime.h>
#include <cuda_bf16.h>
#include <cuda_fp16.h>
#include <cstdint>

// Problem constants (N=170000, E=1200000, IN=HID=128, OUT=40)
#define NN 170000
#define EE 1200000
#define CIN 128
#define CH 128
#define COUT 40
#define SCAN_B 512
#define NBLK ((NN + SCAN_B - 1) / SCAN_B)   // 333
#define KS 136   // smem k-stride (bf16 elems), padded for conflict-free LDSM

// Scratch (static __device__ arrays per allocation rules)
__device__ __half g_h1[(size_t)NN * CH];     // x @ W1 (UNscaled), fp16
__device__ __half g_h2s[(size_t)NN * COUT];  // dis * (h @ W2), fp16
__device__ float g_dis[NN];
__device__ int g_cnt[NN];
__device__ int g_incl[NN];
__device__ int g_start[NN];
__device__ int g_cur[NN];
__device__ volatile int g_flag[NBLK];
__device__ volatile int g_aggv[NBLK];
__device__ volatile int g_pref[NBLK];
__device__ int g_csrc[EE];   // edge srcs grouped by dst

// ---------------------------------------------------------------------------
__global__ void k_zero(int n) {
    int i = blockIdx.x * blockDim.x + threadIdx.x;
    if (i < n) { g_cnt[i] = 0; g_cur[i] = 0; }
    if (i < NBLK) g_flag[i] = 0;
}

// histogram, 4 edges per thread (atomic latency pipelining)
__global__ void k_hist(const int* __restrict__ dst, int e) {
    int base = (blockIdx.x * blockDim.x + threadIdx.x) * 4;
    if (base + 4 <= e) {
        int d0 = dst[base], d1 = dst[base + 1], d2 = dst[base + 2], d3 = dst[base + 3];
        atomicAdd(&g_cnt[d0], 1);
        atomicAdd(&g_cnt[d1], 1);
        atomicAdd(&g_cnt[d2], 1);
        atomicAdd(&g_cnt[d3], 1);
    } else {
        for (int j = base; j < e; ++j) atomicAdd(&g_cnt[dst[j]], 1);
    }
}

// Single-pass inclusive scan of g_cnt (decoupled lookback) + fused dis.
__global__ void k_scanDL(int n) {
    __shared__ int sm[SCAN_B];
    __shared__ int s_excl;
    const int t = threadIdx.x, bid = blockIdx.x;
    const int i = bid * SCAN_B + t;
    int v = (i < n) ? g_cnt[i] : 0;
    sm[t] = v;
    __syncthreads();
#pragma unroll
    for (int off = 1; off < SCAN_B; off <<= 1) {
        int u = (t >= off) ? sm[t - off] : 0;
        __syncthreads();
        sm[t] += u;
        __syncthreads();
    }
    const int incl_local = sm[t];
    const int agg = sm[SCAN_B - 1];

    if (bid == 0) {
        if (t == 0) {
            g_pref[0] = agg;
            __threadfence();
            g_flag[0] = 2;
            s_excl = 0;
        }
    } else {
        if (t == 0) {
            g_aggv[bid] = agg;
            __threadfence();
            g_flag[bid] = 1;
        }
        if (t < 32) {
            int excl = 0;
            for (int base = bid - 1; base >= 0; base -= 32) {
                int j = base - t;
                int f = 0, a = 0;
                if (j >= 0) {
                    while ((f = g_flag[j]) == 0) {}
                    a = (f == 2) ? g_pref[j] : g_aggv[j];
                }
                unsigned done = __ballot_sync(0xffffffffu, (j >= 0) && (f == 2));
                int contrib;
                if (done) {
                    int firstLane = __ffs(done) - 1;
                    contrib = (t <= firstLane) ? a : 0;
                } else {
                    contrib = (j >= 0) ? a : 0;
                }
#pragma unroll
                for (int o = 16; o; o >>= 1) contrib += __shfl_xor_sync(0xffffffffu, contrib, o);
                excl += contrib;
                if (done) break;
            }
            if (t == 0) {
                g_pref[bid] = excl + agg;
                __threadfence();
                g_flag[bid] = 2;
                s_excl = excl;
            }
        }
    }
    __syncthreads();
    const int excl = s_excl;
    if (i < n) {
        int incl = incl_local + excl;
        g_incl[i] = incl;
        g_start[i] = incl - v;
        g_dis[i] = rsqrtf((float)(v + 1));  // +1 self-loop
    }
}

// scatter, 4 edges per thread
__global__ void k_scatter(const int* __restrict__ src, const int* __restrict__ dst, int e) {
    int base = (blockIdx.x * blockDim.x + threadIdx.x) * 4;
    if (base + 4 <= e) {
        int d0 = dst[base], d1 = dst[base + 1], d2 = dst[base + 2], d3 = dst[base + 3];
        int s0 = src[base], s1 = src[base + 1], s2 = src[base + 2], s3 = src[base + 3];
        int p0 = atomicAdd(&g_cur[d0], 1);
        int p1 = atomicAdd(&g_cur[d1], 1);
        int p2 = atomicAdd(&g_cur[d2], 1);
        int p3 = atomicAdd(&g_cur[d3], 1);
        g_csrc[g_start[d0] + p0] = s0;
        g_csrc[g_start[d1] + p1] = s1;
        g_csrc[g_start[d2] + p2] = s2;
        g_csrc[g_start[d3] + p3] = s3;
    } else {
        for (int j = base; j < e; ++j) {
            int d = dst[j];
            int pos = atomicAdd(&g_cur[d], 1);
            g_csrc[g_start[d] + pos] = src[j];
        }
    }
}

// ---------------------------------------------------------------------------
// mma helpers
__device__ __forceinline__ void ldsm_x4(uint32_t* r, uint32_t addr) {
    asm volatile("ldmatrix.sync.aligned.m8n8.x4.shared.b16 {%0,%1,%2,%3}, [%4];"
                 : "=r"(r[0]), "=r"(r[1]), "=r"(r[2]), "=r"(r[3]) : "r"(addr));
}
__device__ __forceinline__ void ldsm_x2(uint32_t* r, uint32_t addr) {
    asm volatile("ldmatrix.sync.aligned.m8n8.x2.shared.b16 {%0,%1}, [%2];"
                 : "=r"(r[0]), "=r"(r[1]) : "r"(addr));
}
__device__ __forceinline__ void mma_bf16(float* d, const uint32_t* a, const uint32_t* b) {
    asm volatile("mma.sync.aligned.m16n8k16.row.col.f32.bf16.bf16.f32 "
                 "{%0,%1,%2,%3}, {%4,%5,%6,%7}, {%8,%9}, {%0,%1,%2,%3};"
                 : "+f"(d[0]), "+f"(d[1]), "+f"(d[2]), "+f"(d[3])
                 : "r"(a[0]), "r"(a[1]), "r"(a[2]), "r"(a[3]), "r"(b[0]), "r"(b[1]));
}

// fp16 4-channel accumulate: acc += w * v
__device__ __forceinline__ void acc4w(float* acc, float w, uint2 raw) {
    float2 f0 = __half22float2(*(__half2*)&raw.x);
    float2 f1 = __half22float2(*(__half2*)&raw.y);
    acc[0] = fmaf(w, f0.x, acc[0]);
    acc[1] = fmaf(w, f0.y, acc[1]);
    acc[2] = fmaf(w, f1.x, acc[2]);
    acc[3] = fmaf(w, f1.y, acc[3]);
}
__device__ __forceinline__ void acc4(float* acc, uint2 raw) {
    float2 f0 = __half22float2(*(__half2*)&raw.x);
    float2 f1 = __half22float2(*(__half2*)&raw.y);
    acc[0] += f0.x; acc[1] += f0.y; acc[2] += f1.x; acc[3] += f1.y;
}

// ---------------------------------------------------------------------------
// GEMM1: bf16-split tensor-core, Y(fp16) = X(fp32)[row,:128] @ W1[:128,128]
__global__ void __launch_bounds__(256, 2)
k_mma1(const float* __restrict__ X, const float* __restrict__ Wg,
       __half* __restrict__ Y, int n) {
    constexpr int CO = 128;
    extern __shared__ char smc[];
    __nv_bfloat16* Ahi = (__nv_bfloat16*)smc;
    __nv_bfloat16* Alo = Ahi + 64 * KS;
    __nv_bfloat16* Whi = Alo + 64 * KS;
    __nv_bfloat16* Wlo = Whi + CO * KS;

    const int t = threadIdx.x;
    const int row0 = blockIdx.x * 64;

    for (int idx = t; idx < 128 * CO; idx += 256) {
        int k = idx / CO, nn_ = idx % CO;
        float v = Wg[k * CO + nn_];
        __nv_bfloat16 h = __float2bfloat16(v);
        __nv_bfloat16 l = __float2bfloat16(v - __bfloat162float(h));
        Whi[nn_ * KS + k] = h;
        Wlo[nn_ * KS + k] = l;
    }
    for (int idx = t; idx < 64 * 32; idx += 256) {
        int r = idx >> 5, c4 = idx & 31;
        int k = c4 * 4;
        float4 v = make_float4(0.f, 0.f, 0.f, 0.f);
        if (row0 + r < n) v = ((const float4*)(X + (size_t)(row0 + r) * 128))[c4];
        __nv_bfloat16 h0 = __float2bfloat16(v.x), h1 = __float2bfloat16(v.y);
        __nv_bfloat16 h2 = __float2bfloat16(v.z), h3 = __float2bfloat16(v.w);
        __nv_bfloat16 l0 = __float2bfloat16(v.x - __bfloat162float(h0));
        __nv_bfloat16 l1 = __float2bfloat16(v.y - __bfloat162float(h1));
        __nv_bfloat16 l2 = __float2bfloat16(v.z - __bfloat162float(h2));
        __nv_bfloat16 l3 = __float2bfloat16(v.w - __bfloat162float(h3));
        *(__nv_bfloat162*)(Ahi + r * KS + k)     = __halves2bfloat162(h0, h1);
        *(__nv_bfloat162*)(Ahi + r * KS + k + 2) = __halves2bfloat162(h2, h3);
        *(__nv_bfloat162*)(Alo + r * KS + k)     = __halves2bfloat162(l0, l1);
        *(__nv_bfloat162*)(Alo + r * KS + k + 2) = __halves2bfloat162(l2, l3);
    }
    __syncthreads();

    const int w = t >> 5, lane = t & 31;
    const int wm = w & 1, wn = w >> 1;
    constexpr int NF = CO / 32;   // 4
    constexpr int WN = CO / 4;    // 32

    uint32_t sbase;
    asm("{ .reg .u64 tt; cvta.to.shared.u64 tt, %1; cvt.u32.u64 %0, tt; }"
        : "=r"(sbase) : "l"(smc));
    const uint32_t aHiB = sbase;
    const uint32_t aLoB = sbase + 64 * KS * 2;
    const uint32_t wHiB = sbase + 2 * 64 * KS * 2;
    const uint32_t wLoB = wHiB + CO * KS * 2;

    uint32_t aOff[2];
#pragma unroll
    for (int mf = 0; mf < 2; mf++) {
        int row = wm * 32 + mf * 16 + (lane & 15);
        aOff[mf] = (uint32_t)(row * KS + ((lane >> 4) << 3)) * 2;
    }
    uint32_t bOff[NF];
#pragma unroll
    for (int nf = 0; nf < NF; nf++) {
        int nr = wn * WN + nf * 8 + (lane & 7);
        bOff[nf] = (uint32_t)(nr * KS + (lane & 8)) * 2;
    }

    float acc[2][NF][4];
#pragma unroll
    for (int mf = 0; mf < 2; mf++)
#pragma unroll
        for (int nf = 0; nf < NF; nf++)
#pragma unroll
            for (int i = 0; i < 4; i++) acc[mf][nf][i] = 0.f;

#pragma unroll
    for (int ks = 0; ks < 8; ks++) {
        const uint32_t kb = ks * 16 * 2;
        uint32_t ah[2][4], al[2][4], bh[NF][2], bl[NF][2];
#pragma unroll
        for (int mf = 0; mf < 2; mf++) {
            ldsm_x4(ah[mf], aHiB + aOff[mf] + kb);
            ldsm_x4(al[mf], aLoB + aOff[mf] + kb);
        }
#pragma unroll
        for (int nf = 0; nf < NF; nf++) {
            ldsm_x2(bh[nf], wHiB + bOff[nf] + kb);
            ldsm_x2(bl[nf], wLoB + bOff[nf] + kb);
        }
#pragma unroll
        for (int mf = 0; mf < 2; mf++)
#pragma unroll
            for (int nf = 0; nf < NF; nf++) {
                mma_bf16(acc[mf][nf], ah[mf], bh[nf]);
                mma_bf16(acc[mf][nf], ah[mf], bl[nf]);
                mma_bf16(acc[mf][nf], al[mf], bh[nf]);
            }
    }

#pragma unroll
    for (int mf = 0; mf < 2; mf++) {
        int rowA = row0 + wm * 32 + mf * 16 + (lane >> 2);
        int rowB = rowA + 8;
#pragma unroll
        for (int nf = 0; nf < NF; nf++) {
            int col = wn * WN + nf * 8 + ((lane & 3) << 1);
            if (rowA < n) {
                __half2 v = __floats2half2_rn(acc[mf][nf][0], acc[mf][nf][1]);
                *(__half2*)(Y + (size_t)rowA * CO + col) = v;
            }
            if (rowB < n) {
                __half2 v = __floats2half2_rn(acc[mf][nf][2], acc[mf][nf][3]);
                *(__half2*)(Y + (size_t)rowB * CO + col) = v;
            }
        }
    }
}

// ---------------------------------------------------------------------------
// FUSED layer-1 aggregation + layer-2 GEMM:
// per 64-node tile: warp-per-row CSR gather of h1 (w/ dis[s]) -> relu(dis*acc+b1)
// -> bf16 hi/lo in smem -> MMA with W2 -> g_h2s = dis * (h @ W2), fp16.
__global__ void __launch_bounds__(256, 2)
k_aggmm(const float* __restrict__ b1, const float* __restrict__ Wg, int wcols,
        __half* __restrict__ Y, int n) {
    constexpr int CO = 64;
    extern __shared__ char smc[];
    __nv_bfloat16* Ahi = (__nv_bfloat16*)smc;
    __nv_bfloat16* Alo = Ahi + 64 * KS;
    __nv_bfloat16* Whi = Alo + 64 * KS;
    __nv_bfloat16* Wlo = Whi + CO * KS;

    const int t = threadIdx.x;
    const int row0 = blockIdx.x * 64;
    const int w = t >> 5, lane = t & 31;

    // W2 transposed into smem (zero-padded cols >= wcols)
    for (int idx = t; idx < 128 * CO; idx += 256) {
        int k = idx / CO, nn_ = idx % CO;
        float v = (nn_ < wcols) ? Wg[k * wcols + nn_] : 0.f;
        __nv_bfloat16 h = __float2bfloat16(v);
        __nv_bfloat16 l = __float2bfloat16(v - __bfloat162float(h));
        Whi[nn_ * KS + k] = h;
        Wlo[nn_ * KS + k] = l;
    }

    // gather phase: warp per row, 8 rows per warp; 4 ch/lane
    const float4 b = ((const float4*)b1)[lane];
    for (int r = w; r < 64; r += 8) {
        int node = row0 + r;
        float o0 = 0.f, o1 = 0.f, o2 = 0.f, o3 = 0.f;
        if (node < n) {
            int end = g_incl[node];
            int p = end - g_cnt[node];
            float acc[4] = {0.f, 0.f, 0.f, 0.f};
            for (; p + 8 <= end; p += 8) {
                int s[8];
#pragma unroll
                for (int j = 0; j < 8; j++) s[j] = g_csrc[p + j];
                float ww[8];
#pragma unroll
                for (int j = 0; j < 8; j++) ww[j] = g_dis[s[j]];
                uint2 rr[8];
#pragma unroll
                for (int j = 0; j < 8; j++)
                    rr[j] = *(const uint2*)(g_h1 + (size_t)s[j] * CH + lane * 4);
#pragma unroll
                for (int j = 0; j < 8; j++) acc4w(acc, ww[j], rr[j]);
            }
            for (; p < end; ++p) {
                int s = g_csrc[p];
                acc4w(acc, g_dis[s], *(const uint2*)(g_h1 + (size_t)s * CH + lane * 4));
            }
            float di = g_dis[node];
            acc4w(acc, di, *(const uint2*)(g_h1 + (size_t)node * CH + lane * 4));
            o0 = fmaxf(fmaf(di, acc[0], b.x), 0.f);
            o1 = fmaxf(fmaf(di, acc[1], b.y), 0.f);
            o2 = fmaxf(fmaf(di, acc[2], b.z), 0.f);
            o3 = fmaxf(fmaf(di, acc[3], b.w), 0.f);
        }
        __nv_bfloat16 h0 = __float2bfloat16(o0), h1_ = __float2bfloat16(o1);
        __nv_bfloat16 h2 = __float2bfloat16(o2), h3 = __float2bfloat16(o3);
        __nv_bfloat16 l0 = __float2bfloat16(o0 - __bfloat162float(h0));
        __nv_bfloat16 l1 = __float2bfloat16(o1 - __bfloat162float(h1_));
        __nv_bfloat16 l2 = __float2bfloat16(o2 - __bfloat162float(h2));
        __nv_bfloat16 l3 = __float2bfloat16(o3 - __bfloat162float(h3));
        int k = lane * 4;
        *(__nv_bfloat162*)(Ahi + r * KS + k)     = __halves2bfloat162(h0, h1_);
        *(__nv_bfloat162*)(Ahi + r * KS + k + 2) = __halves2bfloat162(h2, h3);
        *(__nv_bfloat162*)(Alo + r * KS + k)     = __halves2bfloat162(l0, l1);
        *(__nv_bfloat162*)(Alo + r * KS + k + 2) = __halves2bfloat162(l2, l3);
    }
    __syncthreads();

    // MMA phase
    const int wm = w & 1, wn = w >> 1;
    constexpr int NF = CO / 32;   // 2
    constexpr int WN = CO / 4;    // 16

    uint32_t sbase;
    asm("{ .reg .u64 tt; cvta.to.shared.u64 tt, %1; cvt.u32.u64 %0, tt; }"
        : "=r"(sbase) : "l"(smc));
    const uint32_t aHiB = sbase;
    const uint32_t aLoB = sbase + 64 * KS * 2;
    const uint32_t wHiB = sbase + 2 * 64 * KS * 2;
    const uint32_t wLoB = wHiB + CO * KS * 2;

    uint32_t aOff[2];
#pragma unroll
    for (int mf = 0; mf < 2; mf++) {
        int row = wm * 32 + mf * 16 + (lane & 15);
        aOff[mf] = (uint32_t)(row * KS + ((lane >> 4) << 3)) * 2;
    }
    uint32_t bOff[NF];
#pragma unroll
    for (int nf = 0; nf < NF; nf++) {
        int nr = wn * WN + nf * 8 + (lane & 7);
        bOff[nf] = (uint32_t)(nr * KS + (lane & 8)) * 2;
    }

    float acc[2][NF][4];
#pragma unroll
    for (int mf = 0; mf < 2; mf++)
#pragma unroll
        for (int nf = 0; nf < NF; nf++)
#pragma unroll
            for (int i = 0; i < 4; i++) acc[mf][nf][i] = 0.f;

#pragma unroll
    for (int ks = 0; ks < 8; ks++) {
        const uint32_t kb = ks * 16 * 2;
        uint32_t ah[2][4], al[2][4], bh[NF][2], bl[NF][2];
#pragma unroll
        for (int mf = 0; mf < 2; mf++) {
            ldsm_x4(ah[mf], aHiB + aOff[mf] + kb);
            ldsm_x4(al[mf], aLoB + aOff[mf] + kb);
        }
#pragma unroll
        for (int nf = 0; nf < NF; nf++) {
            ldsm_x2(bh[nf], wHiB + bOff[nf] + kb);
            ldsm_x2(bl[nf], wLoB + bOff[nf] + kb);
        }
#pragma unroll
        for (int mf = 0; mf < 2; mf++)
#pragma unroll
            for (int nf = 0; nf < NF; nf++) {
                mma_bf16(acc[mf][nf], ah[mf], bh[nf]);
                mma_bf16(acc[mf][nf], ah[mf], bl[nf]);
                mma_bf16(acc[mf][nf], al[mf], bh[nf]);
            }
    }

    // epilogue: scale row by dis, fp16 store to g_h2s
#pragma unroll
    for (int mf = 0; mf < 2; mf++) {
        int rowA = row0 + wm * 32 + mf * 16 + (lane >> 2);
        int rowB = rowA + 8;
        float dA = (rowA < n) ? g_dis[rowA] : 0.f;
        float dB = (rowB < n) ? g_dis[rowB] : 0.f;
#pragma unroll
        for (int nf = 0; nf < NF; nf++) {
            int col = wn * WN + nf * 8 + ((lane & 3) << 1);
            if (col >= wcols) continue;
            if (rowA < n) {
                __half2 v = __floats2half2_rn(acc[mf][nf][0] * dA, acc[mf][nf][1] * dA);
                *(__half2*)(Y + (size_t)rowA * wcols + col) = v;
            }
            if (rowB < n) {
                __half2 v = __floats2half2_rn(acc[mf][nf][2] * dB, acc[mf][nf][3] * dB);
                *(__half2*)(Y + (size_t)rowB * wcols + col) = v;
            }
        }
    }
}

// ---------------------------------------------------------------------------
// Layer-2 aggregation (h2s pre-scaled, fp16), fused self-loop+bias; fp32 out.
__global__ void k_aggB(const float* __restrict__ b2, float* __restrict__ out, int n) {
    int g = blockIdx.x * blockDim.x + threadIdx.x;
    int node = g / 10, l = g % 10;
    if (node >= n) return;
    int end = g_incl[node];
    int p = end - g_cnt[node];
    float acc[4] = {0.f, 0.f, 0.f, 0.f};
    for (; p + 4 <= end; p += 4) {
        int s0 = g_csrc[p], s1 = g_csrc[p + 1], s2 = g_csrc[p + 2], s3 = g_csrc[p + 3];
        uint2 r0 = *(const uint2*)(g_h2s + (size_t)s0 * COUT + l * 4);
        uint2 r1 = *(const uint2*)(g_h2s + (size_t)s1 * COUT + l * 4);
        uint2 r2 = *(const uint2*)(g_h2s + (size_t)s2 * COUT + l * 4);
        uint2 r3 = *(const uint2*)(g_h2s + (size_t)s3 * COUT + l * 4);
        acc4(acc, r0); acc4(acc, r1); acc4(acc, r2); acc4(acc, r3);
    }
    for (; p < end; ++p) {
        int s = g_csrc[p];
        acc4(acc, *(const uint2*)(g_h2s + (size_t)s * COUT + l * 4));
    }
    acc4(acc, *(const uint2*)(g_h2s + (size_t)node * COUT + l * 4));
    float di = g_dis[node];
    float4 b = *(const float4*)(b2 + l * 4);
    float4 r;
    r.x = fmaf(di, acc[0], b.x);
    r.y = fmaf(di, acc[1], b.y);
    r.z = fmaf(di, acc[2], b.z);
    r.w = fmaf(di, acc[3], b.w);
    *(float4*)(out + (size_t)node * COUT + l * 4) = r;
}

// ---------------------------------------------------------------------------
extern "C" void kernel_launch(void* const* d_in, const int* in_sizes, int n_in,
                              void* d_out, int out_size) {
    const float* x  = (const float*)d_in[0];
    const float* W1 = (const float*)d_in[1];
    const float* b1 = (const float*)d_in[2];
    const float* W2 = (const float*)d_in[3];
    const float* b2 = (const float*)d_in[4];
    const int* edge = (const int*)d_in[5];

    const int n = in_sizes[0] / CIN;
    const int e = in_sizes[5] / 2;
    const int* src = edge;
    const int* dst = edge + e;
    float* out = (float*)d_out;

    __half *p_h1 = nullptr, *p_h2s = nullptr;
    cudaGetSymbolAddress((void**)&p_h1, g_h1);
    cudaGetSymbolAddress((void**)&p_h2s, g_h2s);

    const int smem1 = (2 * 64 * KS + 2 * 128 * KS) * 2;  // 104448 B
    const int smem2 = (2 * 64 * KS + 2 * 64 * KS) * 2;   // 69632 B
    cudaFuncSetAttribute(k_mma1,  cudaFuncAttributeMaxDynamicSharedMemorySize, smem1);
    cudaFuncSetAttribute(k_aggmm, cudaFuncAttributeMaxDynamicSharedMemorySize, smem2);

    static cudaStream_t s1 = nullptr, s2 = nullptr;
    static cudaEvent_t evFork = nullptr, evJoin = nullptr, evDone = nullptr;
    if (s1 == nullptr) {
        cudaStreamCreateWithFlags(&s1, cudaStreamNonBlocking);
        cudaStreamCreateWithFlags(&s2, cudaStreamNonBlocking);
        cudaEventCreateWithFlags(&evFork, cudaEventDisableTiming);
        cudaEventCreateWithFlags(&evJoin, cudaEventDisableTiming);
        cudaEventCreateWithFlags(&evDone, cudaEventDisableTiming);
    }

    // Fork into s1 (GEMM chain) and s2 (CSR).
    cudaEventRecord(evFork, 0);
    cudaStreamWaitEvent(s1, evFork, 0);
    cudaStreamWaitEvent(s2, evFork, 0);

    // CSR branch (overlaps with GEMM1)
    k_zero<<<(n + 255) / 256, 256, 0, s2>>>(n);
    k_hist<<<(e / 4 + 256) / 256, 256, 0, s2>>>(dst, e);
    k_scanDL<<<NBLK, SCAN_B, 0, s2>>>(n);
    k_scatter<<<(e / 4 + 256) / 256, 256, 0, s2>>>(src, dst, e);
    cudaEventRecord(evJoin, s2);

    // GEMM1 branch
    k_mma1<<<(n + 63) / 64, 256, smem1, s1>>>(x, W1, p_h1, n);

    // Join: fused agg+GEMM2 needs CSR + dis + h1
    cudaStreamWaitEvent(s1, evJoin, 0);
    k_aggmm<<<(n + 63) / 64, 256, smem2, s1>>>(b1, W2, COUT, p_h2s, n);

    k_aggB<<<(int)(((size_t)n * 10 + 319) / 320), 320, 0, s1>>>(b2, out, n);

    // Join back to the launch stream.
    cudaEventRecord(evDone, s1);
    cudaStreamWaitEvent(0, evDone, 0);
}